// round 6
// baseline (speedup 1.0000x reference)
#include <cuda_runtime.h>
#include <cuda_fp16.h>
#include <cstdint>
#include <math.h>

#define BB 4
#define SS 4096
#define EE 512

// ---------------------------------------------------------------------------
// Scratch (__device__ globals; allocation-free rule)
// ---------------------------------------------------------------------------
__device__ __half g_xq_hi[(size_t)BB*SS*EE], g_xq_lo[(size_t)BB*SS*EE];
__device__ __half g_xk_hi[(size_t)BB*SS*EE], g_xk_lo[(size_t)BB*SS*EE];
__device__ __half g_xv_hi[(size_t)BB*SS*EE];
__device__ __half g_wq_hi[(size_t)EE*EE],    g_wq_lo[(size_t)EE*EE];
__device__ __half g_wk_hi[(size_t)EE*EE],    g_wk_lo[(size_t)EE*EE];
__device__ __half g_wv_hi[(size_t)EE*EE],    g_wv_lo[(size_t)EE*EE];
__device__ __half g_q_hi[(size_t)BB*SS*EE],  g_q_lo[(size_t)BB*SS*EE];
__device__ __half g_k_hi[(size_t)BB*SS*EE],  g_k_lo[(size_t)BB*SS*EE];
__device__ __half g_vt[(size_t)BB*EE*SS];
__device__ float  g_scores[(size_t)BB*SS*SS];
__device__ __half g_attn[(size_t)BB*SS*SS];

// ---------------------------------------------------------------------------
// Helpers
// ---------------------------------------------------------------------------
__device__ __forceinline__ uint32_t smem_u32(const void* p) {
    uint32_t a;
    asm("{ .reg .u64 t; cvta.to.shared.u64 t, %1; cvt.u32.u64 %0, t; }"
        : "=r"(a) : "l"(p));
    return a;
}

#define CP_ASYNC16(sm, g) \
    asm volatile("cp.async.cg.shared.global [%0], [%1], 16;" :: "r"(sm), "l"(g))
#define CP_COMMIT() asm volatile("cp.async.commit_group;" ::: "memory")
#define CP_WAIT(n)  asm volatile("cp.async.wait_group %0;" :: "n"(n) : "memory")

__device__ __forceinline__ void ldsm_x4(uint32_t* r, uint32_t addr) {
    asm volatile("ldmatrix.sync.aligned.m8n8.x4.shared.b16 {%0,%1,%2,%3}, [%4];"
        : "=r"(r[0]), "=r"(r[1]), "=r"(r[2]), "=r"(r[3]) : "r"(addr));
}

__device__ __forceinline__ void mma_f16(float* d, const uint32_t* a, const uint32_t* b) {
    asm volatile(
        "mma.sync.aligned.m16n8k16.row.col.f32.f16.f16.f32 "
        "{%0,%1,%2,%3}, {%4,%5,%6,%7}, {%8,%9}, {%0,%1,%2,%3};"
        : "+f"(d[0]), "+f"(d[1]), "+f"(d[2]), "+f"(d[3])
        : "r"(a[0]), "r"(a[1]), "r"(a[2]), "r"(a[3]), "r"(b[0]), "r"(b[1]));
}

// swizzled smem byte offset for a [rows][32 f16] tile (64B rows)
__device__ __forceinline__ uint32_t sw_off(int r, int u) {
    return (uint32_t)(r * 64 + ((u ^ ((r >> 1) & 3)) << 4));
}

__device__ __forceinline__ uint32_t pk2h(__half a, __half b) {
    __half2 t = __halves2half2(a, b);
    return *reinterpret_cast<uint32_t*>(&t);
}

// ---------------------------------------------------------------------------
// HMMA split-fp16 GEMM: C[M,N] = A[M,K] @ B[N,K]^T (+bias), batched (z).
// TERMS: 3 = Ah*Bh + Ah*Bl + Al*Bh, 2 = Ah*Bh + Al*Bh, 1 = Ah*Bh.
// OUT_MODE: 0 fp32, 1 fp16 hi/lo split, 2 fp16 single.
// BIAS_MODE: 0 none, 1 per-N, 2 per-M.
// Block tile 128x256, BK=32, 8 warps (2m x 4n), warp tile 64x64.
// 4-stage cp.async pipeline, prefetch distance 3.
// ---------------------------------------------------------------------------
constexpr int NS = 4;
constexpr int ASZ = 8192;     // 128 rows x 32 cols fp16
constexpr int BSZ = 16384;    // 256 rows x 32 cols fp16
template <int TERMS> struct StgB {
    static constexpr int v = (TERMS == 3) ? (2 * ASZ + 2 * BSZ)
                            : (TERMS == 2) ? (2 * ASZ + BSZ)
                            : (ASZ + BSZ);
};

template <int TERMS, int OUT_MODE, int BIAS_MODE>
__global__ __launch_bounds__(256) void mma_gemm(
    const __half* __restrict__ Ahi, const __half* __restrict__ Alo,
    const __half* __restrict__ Bhi, const __half* __restrict__ Blo,
    const float* __restrict__ bias,
    float* __restrict__ Cf, __half* __restrict__ Ch, __half* __restrict__ Cl,
    int M, int N, int K,
    long long sA, long long sB, long long sC)
{
    constexpr int STG   = StgB<TERMS>::v;
    constexpr int offAl = ASZ;
    constexpr int offBh = (TERMS >= 2) ? 2 * ASZ : ASZ;
    constexpr int offBl = offBh + BSZ;

    extern __shared__ __align__(1024) char smem[];
    const uint32_t sbase = smem_u32(smem);

    const int tid = threadIdx.x;
    const int lane = tid & 31;
    const int wid = tid >> 5;
    const int warp_m = wid & 1;      // 2 groups of 64 rows
    const int warp_n = wid >> 1;     // 4 groups of 64 cols

    const long long bz = blockIdx.z;
    Ahi += bz * sA;  if (TERMS >= 2) Alo += bz * sA;
    Bhi += bz * sB;  if (TERMS == 3) Blo += bz * sB;

    const int row0 = blockIdx.y * 128;
    const int col0 = blockIdx.x * 256;

    float acc[4][8][4];
#pragma unroll
    for (int a = 0; a < 4; a++)
#pragma unroll
        for (int b = 0; b < 8; b++)
#pragma unroll
            for (int c = 0; c < 4; c++) acc[a][b][c] = 0.0f;

    auto issue_stage = [&](int c, int st) {
        const long long k0 = (long long)c * 32;
        const uint32_t s0 = sbase + st * STG;
        // A tile: 128 rows x 32 cols (hi[,lo]) -> 512 float4 per split
#pragma unroll
        for (int i = 0; i < 2; i++) {
            const int f = tid + i * 256;
            const int r = f >> 2, u = f & 3;
            const uint32_t so = sw_off(r, u);
            const long long ga = (long long)(row0 + r) * K + k0 + u * 8;
            CP_ASYNC16(s0 + so, (const void*)(Ahi + ga));
            if (TERMS >= 2) CP_ASYNC16(s0 + offAl + so, (const void*)(Alo + ga));
        }
        // B tile: 256 rows x 32 cols (hi[,lo]) -> 1024 float4 per split
#pragma unroll
        for (int i = 0; i < 4; i++) {
            const int f = tid + i * 256;
            const int r = f >> 2, u = f & 3;
            const uint32_t so = sw_off(r, u);
            const long long gb = (long long)(col0 + r) * K + k0 + u * 8;
            CP_ASYNC16(s0 + offBh + so, (const void*)(Bhi + gb));
            if (TERMS == 3) CP_ASYNC16(s0 + offBl + so, (const void*)(Blo + gb));
        }
    };

    const int nch = K / 32;
    issue_stage(0, 0); CP_COMMIT();
    issue_stage(1, 1); CP_COMMIT();
    issue_stage(2, 2); CP_COMMIT();

    for (int c = 0; c < nch; c++) {
        CP_WAIT(2);
        __syncthreads();
        if (c + 3 < nch) issue_stage(c + 3, (c + 3) & (NS - 1));
        CP_COMMIT();

        const uint32_t s0 = sbase + (c & (NS - 1)) * STG;
#pragma unroll
        for (int ks = 0; ks < 2; ks++) {
            uint32_t ah[4][4], al[4][4], bh[16], bl[16];
#pragma unroll
            for (int mt = 0; mt < 4; mt++) {
                const int r = warp_m * 64 + mt * 16 + (lane & 15);
                const int u = ks * 2 + (lane >> 4);
                const uint32_t ad = s0 + sw_off(r, u);
                ldsm_x4(ah[mt], ad);
                if (TERMS >= 2) ldsm_x4(al[mt], ad + offAl);
            }
#pragma unroll
            for (int g = 0; g < 4; g++) {
                const int r = warp_n * 64 + g * 16 + (lane & 7) + ((lane >> 4) & 1) * 8;
                const int u = ks * 2 + ((lane >> 3) & 1);
                const uint32_t bd = s0 + offBh + sw_off(r, u);
                ldsm_x4(&bh[g * 4], bd);
                if (TERMS == 3) ldsm_x4(&bl[g * 4], bd + BSZ);
            }
#pragma unroll
            for (int mt = 0; mt < 4; mt++)
#pragma unroll
                for (int j = 0; j < 8; j++) {
                    mma_f16(acc[mt][j], ah[mt], &bh[2 * j]);
                    if (TERMS == 3) mma_f16(acc[mt][j], ah[mt], &bl[2 * j]);
                    if (TERMS >= 2) mma_f16(acc[mt][j], al[mt], &bh[2 * j]);
                }
        }
    }

    // ---- epilogue ----
    const long long cb = bz * sC;
#pragma unroll
    for (int mt = 0; mt < 4; mt++) {
        const int rb = row0 + warp_m * 64 + mt * 16 + (lane >> 2);
#pragma unroll
        for (int half = 0; half < 2; half++) {
            const long long row = rb + half * 8;
            float bm = 0.0f;
            if (BIAS_MODE == 2) bm = bias[row];
#pragma unroll
            for (int j = 0; j < 8; j++) {
                const int col = col0 + warp_n * 64 + j * 8 + (lane & 3) * 2;
                float v0 = acc[mt][j][half * 2 + 0] + bm;
                float v1 = acc[mt][j][half * 2 + 1] + bm;
                if (BIAS_MODE == 1) { v0 += bias[col]; v1 += bias[col + 1]; }
                if (OUT_MODE == 1) {
                    const __half h0 = __float2half_rn(v0);
                    const __half h1 = __float2half_rn(v1);
                    const __half l0 = __float2half_rn(v0 - __half2float(h0));
                    const __half l1 = __float2half_rn(v1 - __half2float(h1));
                    *(uint32_t*)(Ch + cb + row * (long long)N + col) = pk2h(h0, h1);
                    *(uint32_t*)(Cl + cb + row * (long long)N + col) = pk2h(l0, l1);
                } else if (OUT_MODE == 2) {
                    *(uint32_t*)(Ch + cb + row * (long long)N + col) =
                        pk2h(__float2half_rn(v0), __float2half_rn(v1));
                } else {
                    float2 vv; vv.x = v0; vv.y = v1;
                    *(float2*)(Cf + cb + row * (long long)N + col) = vv;
                }
            }
        }
    }
}

// ---------------------------------------------------------------------------
// fp32 -> fp16 hi/lo split
// ---------------------------------------------------------------------------
__global__ __launch_bounds__(256) void split2_kernel(
    const float4* __restrict__ in, uint2* __restrict__ hi, uint2* __restrict__ lo, int n4)
{
    const int i = blockIdx.x * 256 + threadIdx.x;
    if (i >= n4) return;
    const float4 v = in[i];
    const __half h0 = __float2half_rn(v.x), h1 = __float2half_rn(v.y);
    const __half h2 = __float2half_rn(v.z), h3 = __float2half_rn(v.w);
    const __half l0 = __float2half_rn(v.x - __half2float(h0));
    const __half l1 = __float2half_rn(v.y - __half2float(h1));
    const __half l2 = __float2half_rn(v.z - __half2float(h2));
    const __half l3 = __float2half_rn(v.w - __half2float(h3));
    uint2 H, L;
    H.x = pk2h(h0, h1); H.y = pk2h(h2, h3);
    L.x = pk2h(l0, l1); L.y = pk2h(l2, l3);
    hi[i] = H;  lo[i] = L;
}

// fp32 -> fp16 single
__global__ __launch_bounds__(256) void cvt1_kernel(
    const float4* __restrict__ in, uint2* __restrict__ hi, int n4)
{
    const int i = blockIdx.x * 256 + threadIdx.x;
    if (i >= n4) return;
    const float4 v = in[i];
    uint2 H;
    H.x = pk2h(__float2half_rn(v.x), __float2half_rn(v.y));
    H.y = pk2h(__float2half_rn(v.z), __float2half_rn(v.w));
    hi[i] = H;
}

// ---------------------------------------------------------------------------
// Softmax over rows of 4096 fp32 scores -> fp16 attn
// ---------------------------------------------------------------------------
__global__ __launch_bounds__(256) void softmax_kernel(
    const float* __restrict__ scores, __half* __restrict__ attn)
{
    const long long row = blockIdx.x;
    const float4* p4 = (const float4*)(scores + row * (long long)SS);
    uint2* h2 = (uint2*)(attn + row * (long long)SS);
    const int tid = threadIdx.x;
    const int lane = tid & 31;
    const int wid = tid >> 5;

    float4 r[4];
    float m = -1e30f;
#pragma unroll
    for (int i = 0; i < 4; i++) {
        r[i] = p4[tid + 256 * i];
        m = fmaxf(m, fmaxf(fmaxf(r[i].x, r[i].y), fmaxf(r[i].z, r[i].w)));
    }
#pragma unroll
    for (int o = 16; o > 0; o >>= 1) m = fmaxf(m, __shfl_xor_sync(0xffffffffu, m, o));
    __shared__ float red[8];
    if (lane == 0) red[wid] = m;
    __syncthreads();
    m = red[0];
#pragma unroll
    for (int i = 1; i < 8; i++) m = fmaxf(m, red[i]);

    float s = 0.0f;
#pragma unroll
    for (int i = 0; i < 4; i++) {
        r[i].x = __expf(r[i].x - m);  r[i].y = __expf(r[i].y - m);
        r[i].z = __expf(r[i].z - m);  r[i].w = __expf(r[i].w - m);
        s += r[i].x + r[i].y + r[i].z + r[i].w;
    }
#pragma unroll
    for (int o = 16; o > 0; o >>= 1) s += __shfl_xor_sync(0xffffffffu, s, o);
    __shared__ float red2[8];
    if (lane == 0) red2[wid] = s;
    __syncthreads();
    s = red2[0];
#pragma unroll
    for (int i = 1; i < 8; i++) s += red2[i];

    const float inv = 1.0f / s;
#pragma unroll
    for (int i = 0; i < 4; i++) {
        uint2 H;
        H.x = pk2h(__float2half_rn(r[i].x * inv), __float2half_rn(r[i].y * inv));
        H.y = pk2h(__float2half_rn(r[i].z * inv), __float2half_rn(r[i].w * inv));
        h2[tid + 256 * i] = H;
    }
}

// ---------------------------------------------------------------------------
extern "C" void kernel_launch(void* const* d_in, const int* in_sizes, int n_in,
                              void* d_out, int out_size)
{
    const float* query = (const float*)d_in[0];
    const float* key   = (const float*)d_in[1];
    const float* value = (const float*)d_in[2];
    const float* Wq    = (const float*)d_in[3];
    const float* bq    = (const float*)d_in[4];
    const float* Wk    = (const float*)d_in[5];
    const float* bk    = (const float*)d_in[6];
    const float* Wv    = (const float*)d_in[7];
    const float* bv    = (const float*)d_in[8];
    float* out = (float*)d_out;

    __half *xq_hi, *xq_lo, *xk_hi, *xk_lo, *xv_hi;
    __half *wq_hi, *wq_lo, *wk_hi, *wk_lo, *wv_hi, *wv_lo;
    __half *q_hi, *q_lo, *k_hi, *k_lo, *vt, *attn;
    float* sc;
    cudaGetSymbolAddress((void**)&xq_hi, g_xq_hi); cudaGetSymbolAddress((void**)&xq_lo, g_xq_lo);
    cudaGetSymbolAddress((void**)&xk_hi, g_xk_hi); cudaGetSymbolAddress((void**)&xk_lo, g_xk_lo);
    cudaGetSymbolAddress((void**)&xv_hi, g_xv_hi);
    cudaGetSymbolAddress((void**)&wq_hi, g_wq_hi); cudaGetSymbolAddress((void**)&wq_lo, g_wq_lo);
    cudaGetSymbolAddress((void**)&wk_hi, g_wk_hi); cudaGetSymbolAddress((void**)&wk_lo, g_wk_lo);
    cudaGetSymbolAddress((void**)&wv_hi, g_wv_hi); cudaGetSymbolAddress((void**)&wv_lo, g_wv_lo);
    cudaGetSymbolAddress((void**)&q_hi,  g_q_hi);  cudaGetSymbolAddress((void**)&q_lo,  g_q_lo);
    cudaGetSymbolAddress((void**)&k_hi,  g_k_hi);  cudaGetSymbolAddress((void**)&k_lo,  g_k_lo);
    cudaGetSymbolAddress((void**)&vt,    g_vt);
    cudaGetSymbolAddress((void**)&attn,  g_attn);
    cudaGetSymbolAddress((void**)&sc,    g_scores);

    cudaFuncSetAttribute(mma_gemm<3, 1, 1>, cudaFuncAttributeMaxDynamicSharedMemorySize, NS * StgB<3>::v);
    cudaFuncSetAttribute(mma_gemm<2, 2, 2>, cudaFuncAttributeMaxDynamicSharedMemorySize, NS * StgB<2>::v);
    cudaFuncSetAttribute(mma_gemm<3, 0, 0>, cudaFuncAttributeMaxDynamicSharedMemorySize, NS * StgB<3>::v);
    cudaFuncSetAttribute(mma_gemm<1, 0, 0>, cudaFuncAttributeMaxDynamicSharedMemorySize, NS * StgB<1>::v);

    const long long nIn = (long long)BB * SS * EE;
    const long long nW  = (long long)EE * EE;
    const long long strideQ = (long long)SS * EE;
    const long long strideS = (long long)SS * SS;
    const long long strideVT = (long long)EE * SS;

    // 1) splits / converts
    split2_kernel<<<(int)(nIn / 4 / 256), 256>>>((const float4*)query, (uint2*)xq_hi, (uint2*)xq_lo, (int)(nIn / 4));
    split2_kernel<<<(int)(nIn / 4 / 256), 256>>>((const float4*)key,   (uint2*)xk_hi, (uint2*)xk_lo, (int)(nIn / 4));
    cvt1_kernel<<<(int)(nIn / 4 / 256), 256>>>((const float4*)value, (uint2*)xv_hi, (int)(nIn / 4));
    split2_kernel<<<(int)(nW / 4 / 256), 256>>>((const float4*)Wq, (uint2*)wq_hi, (uint2*)wq_lo, (int)(nW / 4));
    split2_kernel<<<(int)(nW / 4 / 256), 256>>>((const float4*)Wk, (uint2*)wk_hi, (uint2*)wk_lo, (int)(nW / 4));
    split2_kernel<<<(int)(nW / 4 / 256), 256>>>((const float4*)Wv, (uint2*)wv_hi, (uint2*)wv_lo, (int)(nW / 4));

    // 2) q/k projections (3-term, split fp16 out, per-N bias)
    {
        dim3 g(EE / 256, (BB * SS) / 128, 1);
        mma_gemm<3, 1, 1><<<g, 256, NS * StgB<3>::v>>>(xq_hi, xq_lo, wq_hi, wq_lo, bq,
                                                       nullptr, q_hi, q_lo,
                                                       BB * SS, EE, EE, 0, 0, 0);
        mma_gemm<3, 1, 1><<<g, 256, NS * StgB<3>::v>>>(xk_hi, xk_lo, wk_hi, wk_lo, bk,
                                                       nullptr, k_hi, k_lo,
                                                       BB * SS, EE, EE, 0, 0, 0);
    }

    // 3) v projection, transposed (2-term: Wv split x value single; fp16 out; per-M bias)
    {
        dim3 g(SS / 256, EE / 128, BB);
        mma_gemm<2, 2, 2><<<g, 256, NS * StgB<2>::v>>>(wv_hi, wv_lo, xv_hi, nullptr, bv,
                                                       nullptr, vt, nullptr,
                                                       EE, SS, EE, 0, strideQ, strideVT);
    }

    // 4) scores = q @ k^T (3-term, fp32 out)
    {
        dim3 g(SS / 256, SS / 128, BB);
        mma_gemm<3, 0, 0><<<g, 256, NS * StgB<3>::v>>>(q_hi, q_lo, k_hi, k_lo, nullptr,
                                                       sc, nullptr, nullptr,
                                                       SS, SS, EE, strideQ, strideQ, strideS);
    }

    // 5) softmax -> fp16 attn
    softmax_kernel<<<BB * SS, 256>>>(sc, attn);

    // 6) out = attn @ vt^T (1-term, fp32 out)
    {
        dim3 g(EE / 256, SS / 128, BB);
        mma_gemm<1, 0, 0><<<g, 256, NS * StgB<1>::v>>>(attn, nullptr, vt, nullptr, nullptr,
                                                       out, nullptr, nullptr,
                                                       SS, EE, SS, strideS, strideVT, strideQ);
    }
}

// round 7
// speedup vs baseline: 1.0047x; 1.0047x over previous
#include <cuda_runtime.h>
#include <cuda_fp16.h>
#include <cstdint>
#include <math.h>

#define BB 4
#define SS 4096
#define EE 512

// ---------------------------------------------------------------------------
// Scratch (__device__ globals; allocation-free rule)
// ---------------------------------------------------------------------------
__device__ __half g_xq_hi[(size_t)BB*SS*EE], g_xq_lo[(size_t)BB*SS*EE];
__device__ __half g_xk_hi[(size_t)BB*SS*EE], g_xk_lo[(size_t)BB*SS*EE];
__device__ __half g_xv_hi[(size_t)BB*SS*EE];
__device__ __half g_wq_hi[(size_t)EE*EE],    g_wq_lo[(size_t)EE*EE];
__device__ __half g_wk_hi[(size_t)EE*EE],    g_wk_lo[(size_t)EE*EE];
__device__ __half g_wv_hi[(size_t)EE*EE],    g_wv_lo[(size_t)EE*EE];
__device__ __half g_q_hi[(size_t)BB*SS*EE],  g_q_lo[(size_t)BB*SS*EE];
__device__ __half g_k_hi[(size_t)BB*SS*EE],  g_k_lo[(size_t)BB*SS*EE];
__device__ __half g_vt[(size_t)BB*EE*SS];
__device__ float  g_scores[(size_t)BB*SS*SS];
__device__ __half g_attn[(size_t)BB*SS*SS];

// ---------------------------------------------------------------------------
// Helpers
// ---------------------------------------------------------------------------
__device__ __forceinline__ uint32_t smem_u32(const void* p) {
    uint32_t a;
    asm("{ .reg .u64 t; cvta.to.shared.u64 t, %1; cvt.u32.u64 %0, t; }"
        : "=r"(a) : "l"(p));
    return a;
}

#define CP_ASYNC16(sm, g) \
    asm volatile("cp.async.cg.shared.global [%0], [%1], 16;" :: "r"(sm), "l"(g))
#define CP_COMMIT() asm volatile("cp.async.commit_group;" ::: "memory")
#define CP_WAIT(n)  asm volatile("cp.async.wait_group %0;" :: "n"(n) : "memory")

__device__ __forceinline__ void ldsm_x4(uint32_t* r, uint32_t addr) {
    asm volatile("ldmatrix.sync.aligned.m8n8.x4.shared.b16 {%0,%1,%2,%3}, [%4];"
        : "=r"(r[0]), "=r"(r[1]), "=r"(r[2]), "=r"(r[3]) : "r"(addr));
}

__device__ __forceinline__ void mma_f16(float* d, const uint32_t* a, const uint32_t* b) {
    asm volatile(
        "mma.sync.aligned.m16n8k16.row.col.f32.f16.f16.f32 "
        "{%0,%1,%2,%3}, {%4,%5,%6,%7}, {%8,%9}, {%0,%1,%2,%3};"
        : "+f"(d[0]), "+f"(d[1]), "+f"(d[2]), "+f"(d[3])
        : "r"(a[0]), "r"(a[1]), "r"(a[2]), "r"(a[3]), "r"(b[0]), "r"(b[1]));
}

// swizzled smem byte offset for a [rows][32 f16] tile (64B rows)
__device__ __forceinline__ uint32_t sw_off(int r, int u) {
    return (uint32_t)(r * 64 + ((u ^ ((r >> 1) & 3)) << 4));
}

__device__ __forceinline__ uint32_t pk2h(__half a, __half b) {
    __half2 t = __halves2half2(a, b);
    return *reinterpret_cast<uint32_t*>(&t);
}

// ---------------------------------------------------------------------------
// HMMA split-fp16 GEMM: C[M,N] = A[M,K] @ B[N,K]^T (+bias), batched (z).
// TERMS: 3 = Ah*Bh + Ah*Bl + Al*Bh, 2 = Ah*Bh + Al*Bh, 1 = Ah*Bh.
// OUT_MODE: 0 fp32, 1 fp16 hi/lo split, 2 fp16 single.
// BIAS_MODE: 0 none, 1 per-N, 2 per-M.
// Block tile 256x128, BK=32, 512 threads = 16 warps (8m x 2n), warp 32x64.
// 3-stage cp.async pipeline, prefetch distance 2.
// ---------------------------------------------------------------------------
constexpr int NS = 3;
constexpr int ASZ = 16384;    // 256 rows x 32 cols fp16
constexpr int BSZ = 8192;     // 128 rows x 32 cols fp16
template <int TERMS> struct StgB {
    static constexpr int v = (TERMS == 3) ? (2 * ASZ + 2 * BSZ)
                            : (TERMS == 2) ? (2 * ASZ + BSZ)
                            : (ASZ + BSZ);
};

template <int TERMS, int OUT_MODE, int BIAS_MODE>
__global__ __launch_bounds__(512) void mma_gemm(
    const __half* __restrict__ Ahi, const __half* __restrict__ Alo,
    const __half* __restrict__ Bhi, const __half* __restrict__ Blo,
    const float* __restrict__ bias,
    float* __restrict__ Cf, __half* __restrict__ Ch, __half* __restrict__ Cl,
    int M, int N, int K,
    long long sA, long long sB, long long sC)
{
    constexpr int STG   = StgB<TERMS>::v;
    constexpr int offAl = ASZ;
    constexpr int offBh = (TERMS >= 2) ? 2 * ASZ : ASZ;
    constexpr int offBl = offBh + BSZ;

    extern __shared__ __align__(1024) char smem[];
    const uint32_t sbase = smem_u32(smem);

    const int tid = threadIdx.x;
    const int lane = tid & 31;
    const int wid = tid >> 5;
    const int warp_m = wid & 7;      // 8 groups of 32 rows
    const int warp_n = wid >> 3;     // 2 groups of 64 cols

    const long long bz = blockIdx.z;
    Ahi += bz * sA;  if (TERMS >= 2) Alo += bz * sA;
    Bhi += bz * sB;  if (TERMS == 3) Blo += bz * sB;

    const int row0 = blockIdx.y * 256;
    const int col0 = blockIdx.x * 128;

    float acc[2][8][4];
#pragma unroll
    for (int a = 0; a < 2; a++)
#pragma unroll
        for (int b = 0; b < 8; b++)
#pragma unroll
            for (int c = 0; c < 4; c++) acc[a][b][c] = 0.0f;

    auto issue_stage = [&](int c, int st) {
        const long long k0 = (long long)c * 32;
        const uint32_t s0 = sbase + st * STG;
        // A tile: 256 rows x 32 cols (hi[,lo]) -> 1024 float4 per split
#pragma unroll
        for (int i = 0; i < 2; i++) {
            const int f = tid + i * 512;
            const int r = f >> 2, u = f & 3;
            const uint32_t so = sw_off(r, u);
            const long long ga = (long long)(row0 + r) * K + k0 + u * 8;
            CP_ASYNC16(s0 + so, (const void*)(Ahi + ga));
            if (TERMS >= 2) CP_ASYNC16(s0 + offAl + so, (const void*)(Alo + ga));
        }
        // B tile: 128 rows x 32 cols (hi[,lo]) -> 512 float4 per split
        {
            const int r = tid >> 2, u = tid & 3;
            const uint32_t so = sw_off(r, u);
            const long long gb = (long long)(col0 + r) * K + k0 + u * 8;
            CP_ASYNC16(s0 + offBh + so, (const void*)(Bhi + gb));
            if (TERMS == 3) CP_ASYNC16(s0 + offBl + so, (const void*)(Blo + gb));
        }
    };

    const int nch = K / 32;
    issue_stage(0, 0); CP_COMMIT();
    issue_stage(1, 1); CP_COMMIT();

    for (int c = 0; c < nch; c++) {
        CP_WAIT(1);
        __syncthreads();
        if (c + 2 < nch) issue_stage(c + 2, (c + 2) % NS);
        CP_COMMIT();

        const uint32_t s0 = sbase + (c % NS) * STG;
#pragma unroll
        for (int ks = 0; ks < 2; ks++) {
            uint32_t ah[2][4], al[2][4], bh[16], bl[16];
#pragma unroll
            for (int mt = 0; mt < 2; mt++) {
                const int r = warp_m * 32 + mt * 16 + (lane & 15);
                const int u = ks * 2 + (lane >> 4);
                const uint32_t ad = s0 + sw_off(r, u);
                ldsm_x4(ah[mt], ad);
                if (TERMS >= 2) ldsm_x4(al[mt], ad + offAl);
            }
#pragma unroll
            for (int g = 0; g < 4; g++) {
                const int r = warp_n * 64 + g * 16 + (lane & 7) + ((lane >> 4) & 1) * 8;
                const int u = ks * 2 + ((lane >> 3) & 1);
                const uint32_t bd = s0 + offBh + sw_off(r, u);
                ldsm_x4(&bh[g * 4], bd);
                if (TERMS == 3) ldsm_x4(&bl[g * 4], bd + BSZ);
            }
#pragma unroll
            for (int mt = 0; mt < 2; mt++)
#pragma unroll
                for (int j = 0; j < 8; j++) {
                    mma_f16(acc[mt][j], ah[mt], &bh[2 * j]);
                    if (TERMS == 3) mma_f16(acc[mt][j], ah[mt], &bl[2 * j]);
                    if (TERMS >= 2) mma_f16(acc[mt][j], al[mt], &bh[2 * j]);
                }
        }
    }

    // ---- epilogue ----
    const long long cb = bz * sC;
#pragma unroll
    for (int mt = 0; mt < 2; mt++) {
        const int rb = row0 + warp_m * 32 + mt * 16 + (lane >> 2);
#pragma unroll
        for (int half = 0; half < 2; half++) {
            const long long row = rb + half * 8;
            float bm = 0.0f;
            if (BIAS_MODE == 2) bm = bias[row];
#pragma unroll
            for (int j = 0; j < 8; j++) {
                const int col = col0 + warp_n * 64 + j * 8 + (lane & 3) * 2;
                float v0 = acc[mt][j][half * 2 + 0] + bm;
                float v1 = acc[mt][j][half * 2 + 1] + bm;
                if (BIAS_MODE == 1) { v0 += bias[col]; v1 += bias[col + 1]; }
                if (OUT_MODE == 1) {
                    const __half h0 = __float2half_rn(v0);
                    const __half h1 = __float2half_rn(v1);
                    const __half l0 = __float2half_rn(v0 - __half2float(h0));
                    const __half l1 = __float2half_rn(v1 - __half2float(h1));
                    *(uint32_t*)(Ch + cb + row * (long long)N + col) = pk2h(h0, h1);
                    *(uint32_t*)(Cl + cb + row * (long long)N + col) = pk2h(l0, l1);
                } else if (OUT_MODE == 2) {
                    *(uint32_t*)(Ch + cb + row * (long long)N + col) =
                        pk2h(__float2half_rn(v0), __float2half_rn(v1));
                } else {
                    float2 vv; vv.x = v0; vv.y = v1;
                    *(float2*)(Cf + cb + row * (long long)N + col) = vv;
                }
            }
        }
    }
}

// ---------------------------------------------------------------------------
// fp32 -> fp16 hi/lo split
// ---------------------------------------------------------------------------
__global__ __launch_bounds__(256) void split2_kernel(
    const float4* __restrict__ in, uint2* __restrict__ hi, uint2* __restrict__ lo, int n4)
{
    const int i = blockIdx.x * 256 + threadIdx.x;
    if (i >= n4) return;
    const float4 v = in[i];
    const __half h0 = __float2half_rn(v.x), h1 = __float2half_rn(v.y);
    const __half h2 = __float2half_rn(v.z), h3 = __float2half_rn(v.w);
    const __half l0 = __float2half_rn(v.x - __half2float(h0));
    const __half l1 = __float2half_rn(v.y - __half2float(h1));
    const __half l2 = __float2half_rn(v.z - __half2float(h2));
    const __half l3 = __float2half_rn(v.w - __half2float(h3));
    uint2 H, L;
    H.x = pk2h(h0, h1); H.y = pk2h(h2, h3);
    L.x = pk2h(l0, l1); L.y = pk2h(l2, l3);
    hi[i] = H;  lo[i] = L;
}

// fp32 -> fp16 single
__global__ __launch_bounds__(256) void cvt1_kernel(
    const float4* __restrict__ in, uint2* __restrict__ hi, int n4)
{
    const int i = blockIdx.x * 256 + threadIdx.x;
    if (i >= n4) return;
    const float4 v = in[i];
    uint2 H;
    H.x = pk2h(__float2half_rn(v.x), __float2half_rn(v.y));
    H.y = pk2h(__float2half_rn(v.z), __float2half_rn(v.w));
    hi[i] = H;
}

// ---------------------------------------------------------------------------
// Softmax over rows of 4096 fp32 scores -> fp16 attn
// ---------------------------------------------------------------------------
__global__ __launch_bounds__(256) void softmax_kernel(
    const float* __restrict__ scores, __half* __restrict__ attn)
{
    const long long row = blockIdx.x;
    const float4* p4 = (const float4*)(scores + row * (long long)SS);
    uint2* h2 = (uint2*)(attn + row * (long long)SS);
    const int tid = threadIdx.x;
    const int lane = tid & 31;
    const int wid = tid >> 5;

    float4 r[4];
    float m = -1e30f;
#pragma unroll
    for (int i = 0; i < 4; i++) {
        r[i] = p4[tid + 256 * i];
        m = fmaxf(m, fmaxf(fmaxf(r[i].x, r[i].y), fmaxf(r[i].z, r[i].w)));
    }
#pragma unroll
    for (int o = 16; o > 0; o >>= 1) m = fmaxf(m, __shfl_xor_sync(0xffffffffu, m, o));
    __shared__ float red[8];
    if (lane == 0) red[wid] = m;
    __syncthreads();
    m = red[0];
#pragma unroll
    for (int i = 1; i < 8; i++) m = fmaxf(m, red[i]);

    float s = 0.0f;
#pragma unroll
    for (int i = 0; i < 4; i++) {
        r[i].x = __expf(r[i].x - m);  r[i].y = __expf(r[i].y - m);
        r[i].z = __expf(r[i].z - m);  r[i].w = __expf(r[i].w - m);
        s += r[i].x + r[i].y + r[i].z + r[i].w;
    }
#pragma unroll
    for (int o = 16; o > 0; o >>= 1) s += __shfl_xor_sync(0xffffffffu, s, o);
    __shared__ float red2[8];
    if (lane == 0) red2[wid] = s;
    __syncthreads();
    s = red2[0];
#pragma unroll
    for (int i = 1; i < 8; i++) s += red2[i];

    const float inv = 1.0f / s;
#pragma unroll
    for (int i = 0; i < 4; i++) {
        uint2 H;
        H.x = pk2h(__float2half_rn(r[i].x * inv), __float2half_rn(r[i].y * inv));
        H.y = pk2h(__float2half_rn(r[i].z * inv), __float2half_rn(r[i].w * inv));
        h2[tid + 256 * i] = H;
    }
}

// ---------------------------------------------------------------------------
extern "C" void kernel_launch(void* const* d_in, const int* in_sizes, int n_in,
                              void* d_out, int out_size)
{
    const float* query = (const float*)d_in[0];
    const float* key   = (const float*)d_in[1];
    const float* value = (const float*)d_in[2];
    const float* Wq    = (const float*)d_in[3];
    const float* bq    = (const float*)d_in[4];
    const float* Wk    = (const float*)d_in[5];
    const float* bk    = (const float*)d_in[6];
    const float* Wv    = (const float*)d_in[7];
    const float* bv    = (const float*)d_in[8];
    float* out = (float*)d_out;

    __half *xq_hi, *xq_lo, *xk_hi, *xk_lo, *xv_hi;
    __half *wq_hi, *wq_lo, *wk_hi, *wk_lo, *wv_hi, *wv_lo;
    __half *q_hi, *q_lo, *k_hi, *k_lo, *vt, *attn;
    float* sc;
    cudaGetSymbolAddress((void**)&xq_hi, g_xq_hi); cudaGetSymbolAddress((void**)&xq_lo, g_xq_lo);
    cudaGetSymbolAddress((void**)&xk_hi, g_xk_hi); cudaGetSymbolAddress((void**)&xk_lo, g_xk_lo);
    cudaGetSymbolAddress((void**)&xv_hi, g_xv_hi);
    cudaGetSymbolAddress((void**)&wq_hi, g_wq_hi); cudaGetSymbolAddress((void**)&wq_lo, g_wq_lo);
    cudaGetSymbolAddress((void**)&wk_hi, g_wk_hi); cudaGetSymbolAddress((void**)&wk_lo, g_wk_lo);
    cudaGetSymbolAddress((void**)&wv_hi, g_wv_hi); cudaGetSymbolAddress((void**)&wv_lo, g_wv_lo);
    cudaGetSymbolAddress((void**)&q_hi,  g_q_hi);  cudaGetSymbolAddress((void**)&q_lo,  g_q_lo);
    cudaGetSymbolAddress((void**)&k_hi,  g_k_hi);  cudaGetSymbolAddress((void**)&k_lo,  g_k_lo);
    cudaGetSymbolAddress((void**)&vt,    g_vt);
    cudaGetSymbolAddress((void**)&attn,  g_attn);
    cudaGetSymbolAddress((void**)&sc,    g_scores);

    cudaFuncSetAttribute(mma_gemm<3, 1, 1>, cudaFuncAttributeMaxDynamicSharedMemorySize, NS * StgB<3>::v);
    cudaFuncSetAttribute(mma_gemm<2, 2, 2>, cudaFuncAttributeMaxDynamicSharedMemorySize, NS * StgB<2>::v);
    cudaFuncSetAttribute(mma_gemm<3, 0, 0>, cudaFuncAttributeMaxDynamicSharedMemorySize, NS * StgB<3>::v);
    cudaFuncSetAttribute(mma_gemm<1, 0, 0>, cudaFuncAttributeMaxDynamicSharedMemorySize, NS * StgB<1>::v);

    const long long nIn = (long long)BB * SS * EE;
    const long long nW  = (long long)EE * EE;
    const long long strideQ = (long long)SS * EE;
    const long long strideS = (long long)SS * SS;
    const long long strideVT = (long long)EE * SS;

    // 1) splits / converts
    split2_kernel<<<(int)(nIn / 4 / 256), 256>>>((const float4*)query, (uint2*)xq_hi, (uint2*)xq_lo, (int)(nIn / 4));
    split2_kernel<<<(int)(nIn / 4 / 256), 256>>>((const float4*)key,   (uint2*)xk_hi, (uint2*)xk_lo, (int)(nIn / 4));
    cvt1_kernel<<<(int)(nIn / 4 / 256), 256>>>((const float4*)value, (uint2*)xv_hi, (int)(nIn / 4));
    split2_kernel<<<(int)(nW / 4 / 256), 256>>>((const float4*)Wq, (uint2*)wq_hi, (uint2*)wq_lo, (int)(nW / 4));
    split2_kernel<<<(int)(nW / 4 / 256), 256>>>((const float4*)Wk, (uint2*)wk_hi, (uint2*)wk_lo, (int)(nW / 4));
    split2_kernel<<<(int)(nW / 4 / 256), 256>>>((const float4*)Wv, (uint2*)wv_hi, (uint2*)wv_lo, (int)(nW / 4));

    // 2) q/k projections (3-term, split fp16 out, per-N bias)  M=16384 N=512
    {
        dim3 g(EE / 128, (BB * SS) / 256, 1);
        mma_gemm<3, 1, 1><<<g, 512, NS * StgB<3>::v>>>(xq_hi, xq_lo, wq_hi, wq_lo, bq,
                                                       nullptr, q_hi, q_lo,
                                                       BB * SS, EE, EE, 0, 0, 0);
        mma_gemm<3, 1, 1><<<g, 512, NS * StgB<3>::v>>>(xk_hi, xk_lo, wk_hi, wk_lo, bk,
                                                       nullptr, k_hi, k_lo,
                                                       BB * SS, EE, EE, 0, 0, 0);
    }

    // 3) v projection, transposed (2-term; fp16 out; per-M bias)  M=512 N=4096
    {
        dim3 g(SS / 128, EE / 256, BB);
        mma_gemm<2, 2, 2><<<g, 512, NS * StgB<2>::v>>>(wv_hi, wv_lo, xv_hi, nullptr, bv,
                                                       nullptr, vt, nullptr,
                                                       EE, SS, EE, 0, strideQ, strideVT);
    }

    // 4) scores = q @ k^T (3-term, fp32 out)  M=N=4096
    {
        dim3 g(SS / 128, SS / 256, BB);
        mma_gemm<3, 0, 0><<<g, 512, NS * StgB<3>::v>>>(q_hi, q_lo, k_hi, k_lo, nullptr,
                                                       sc, nullptr, nullptr,
                                                       SS, SS, EE, strideQ, strideQ, strideS);
    }

    // 5) softmax -> fp16 attn
    softmax_kernel<<<BB * SS, 256>>>(sc, attn);

    // 6) out = attn @ vt^T (1-term, fp32 out)  M=4096 N=512
    {
        dim3 g(EE / 128, SS / 256, BB);
        mma_gemm<1, 0, 0><<<g, 512, NS * StgB<1>::v>>>(attn, nullptr, vt, nullptr, nullptr,
                                                       out, nullptr, nullptr,
                                                       SS, EE, SS, strideS, strideVT, strideQ);
    }
}

// round 8
// speedup vs baseline: 1.1247x; 1.1195x over previous
#include <cuda_runtime.h>
#include <cuda_fp16.h>
#include <cstdint>
#include <math.h>

#define BB 4
#define SS 4096
#define EE 512

// ---------------------------------------------------------------------------
// Scratch (__device__ globals; allocation-free rule)
// ---------------------------------------------------------------------------
__device__ __half g_xq_hi[(size_t)BB*SS*EE], g_xq_lo[(size_t)BB*SS*EE];
__device__ __half g_xk_hi[(size_t)BB*SS*EE], g_xk_lo[(size_t)BB*SS*EE];
__device__ __half g_xv_hi[(size_t)BB*SS*EE];
__device__ __half g_wq_hi[(size_t)EE*EE],    g_wq_lo[(size_t)EE*EE];
__device__ __half g_wk_hi[(size_t)EE*EE],    g_wk_lo[(size_t)EE*EE];
__device__ __half g_wv_hi[(size_t)EE*EE],    g_wv_lo[(size_t)EE*EE];
__device__ __half g_q_hi[(size_t)BB*SS*EE],  g_q_lo[(size_t)BB*SS*EE];
__device__ __half g_k_hi[(size_t)BB*SS*EE],  g_k_lo[(size_t)BB*SS*EE];
__device__ __half g_vt[(size_t)BB*EE*SS];
__device__ float  g_scores[(size_t)BB*SS*SS];
__device__ __half g_attn[(size_t)BB*SS*SS];

// ---------------------------------------------------------------------------
// Helpers
// ---------------------------------------------------------------------------
__device__ __forceinline__ uint32_t smem_u32(const void* p) {
    uint32_t a;
    asm("{ .reg .u64 t; cvta.to.shared.u64 t, %1; cvt.u32.u64 %0, t; }"
        : "=r"(a) : "l"(p));
    return a;
}

#define CP_ASYNC16(sm, g) \
    asm volatile("cp.async.cg.shared.global [%0], [%1], 16;" :: "r"(sm), "l"(g))
#define CP_COMMIT() asm volatile("cp.async.commit_group;" ::: "memory")
#define CP_WAIT(n)  asm volatile("cp.async.wait_group %0;" :: "n"(n) : "memory")

__device__ __forceinline__ void ldsm_x4(uint32_t* r, uint32_t addr) {
    asm volatile("ldmatrix.sync.aligned.m8n8.x4.shared.b16 {%0,%1,%2,%3}, [%4];"
        : "=r"(r[0]), "=r"(r[1]), "=r"(r[2]), "=r"(r[3]) : "r"(addr));
}

__device__ __forceinline__ void mma_f16(float* d, const uint32_t* a, const uint32_t* b) {
    asm volatile(
        "mma.sync.aligned.m16n8k16.row.col.f32.f16.f16.f32 "
        "{%0,%1,%2,%3}, {%4,%5,%6,%7}, {%8,%9}, {%0,%1,%2,%3};"
        : "+f"(d[0]), "+f"(d[1]), "+f"(d[2]), "+f"(d[3])
        : "r"(a[0]), "r"(a[1]), "r"(a[2]), "r"(a[3]), "r"(b[0]), "r"(b[1]));
}

// swizzled smem byte offset for a [rows][32 f16] tile (64B rows)
__device__ __forceinline__ uint32_t sw_off(int r, int u) {
    return (uint32_t)(r * 64 + ((u ^ ((r >> 1) & 3)) << 4));
}

__device__ __forceinline__ uint32_t pk2h(__half a, __half b) {
    __half2 t = __halves2half2(a, b);
    return *reinterpret_cast<uint32_t*>(&t);
}

// ---------------------------------------------------------------------------
// HMMA split-fp16 GEMM: C[M,N] = A[M,K] @ B[N,K]^T (+bias), batched (z).
// TERMS: 3 = Ah*Bh + Ah*Bl + Al*Bh, 2 = Ah*Bh + Al*Bh, 1 = Ah*Bh.
// OUT_MODE: 0 fp32, 1 fp16 hi/lo split, 2 fp16 single.
// BIAS_MODE: 0 none, 1 per-N, 2 per-M.
// Block tile 128x128, BK=32, 8 warps (4m x 2n), warp tile 32x64.
// 3-stage cp.async pipeline; __launch_bounds__(256,2) caps regs at 128
// to guarantee 2 CTAs/SM residency (192KB smem <= 228KB).
// ---------------------------------------------------------------------------
constexpr int NS = 3;
template <int TERMS> struct StgB { static constexpr int v = 8192 * (TERMS == 3 ? 4 : TERMS == 2 ? 3 : 2); };

template <int TERMS, int OUT_MODE, int BIAS_MODE>
__global__ __launch_bounds__(256, 2) void mma_gemm(
    const __half* __restrict__ Ahi, const __half* __restrict__ Alo,
    const __half* __restrict__ Bhi, const __half* __restrict__ Blo,
    const float* __restrict__ bias,
    float* __restrict__ Cf, __half* __restrict__ Ch, __half* __restrict__ Cl,
    int M, int N, int K,
    long long sA, long long sB, long long sC)
{
    constexpr int STG   = StgB<TERMS>::v;
    constexpr int offAl = 8192;
    constexpr int offBh = (TERMS >= 2) ? 16384 : 8192;
    constexpr int offBl = offBh + 8192;

    extern __shared__ __align__(1024) char smem[];
    const uint32_t sbase = smem_u32(smem);

    const int tid = threadIdx.x;
    const int lane = tid & 31;
    const int wid = tid >> 5;
    const int warp_m = wid & 3;
    const int warp_n = wid >> 2;

    const long long bz = blockIdx.z;
    Ahi += bz * sA;  if (TERMS >= 2) Alo += bz * sA;
    Bhi += bz * sB;  if (TERMS == 3) Blo += bz * sB;

    const int row0 = blockIdx.y * 128;
    const int col0 = blockIdx.x * 128;

    float acc[2][8][4];
#pragma unroll
    for (int a = 0; a < 2; a++)
#pragma unroll
        for (int b = 0; b < 8; b++)
#pragma unroll
            for (int c = 0; c < 4; c++) acc[a][b][c] = 0.0f;

    auto issue_stage = [&](int c, int st) {
        const long long k0 = (long long)c * 32;
        const uint32_t s0 = sbase + st * STG;
#pragma unroll
        for (int i = 0; i < 2; i++) {
            const int f = tid + i * 256;
            const int r = f >> 2, u = f & 3;
            const uint32_t so = sw_off(r, u);
            const long long ga = (long long)(row0 + r) * K + k0 + u * 8;
            const long long gb = (long long)(col0 + r) * K + k0 + u * 8;
            CP_ASYNC16(s0 + so, (const void*)(Ahi + ga));
            if (TERMS >= 2) CP_ASYNC16(s0 + offAl + so, (const void*)(Alo + ga));
            CP_ASYNC16(s0 + offBh + so, (const void*)(Bhi + gb));
            if (TERMS == 3) CP_ASYNC16(s0 + offBl + so, (const void*)(Blo + gb));
        }
    };

    const int nch = K / 32;
    issue_stage(0, 0); CP_COMMIT();
    issue_stage(1, 1); CP_COMMIT();

    for (int c = 0; c < nch; c++) {
        CP_WAIT(1);
        __syncthreads();
        if (c + 2 < nch) issue_stage(c + 2, (c + 2) % NS);
        CP_COMMIT();

        const uint32_t s0 = sbase + (c % NS) * STG;
#pragma unroll
        for (int ks = 0; ks < 2; ks++) {
            uint32_t ah[2][4], al[2][4], bh[16], bl[16];
#pragma unroll
            for (int mt = 0; mt < 2; mt++) {
                const int r = warp_m * 32 + mt * 16 + (lane & 15);
                const int u = ks * 2 + (lane >> 4);
                const uint32_t ad = s0 + sw_off(r, u);
                ldsm_x4(ah[mt], ad);
                if (TERMS >= 2) ldsm_x4(al[mt], ad + offAl);
            }
#pragma unroll
            for (int g = 0; g < 4; g++) {
                const int r = warp_n * 64 + g * 16 + (lane & 7) + ((lane >> 4) & 1) * 8;
                const int u = ks * 2 + ((lane >> 3) & 1);
                const uint32_t bd = s0 + offBh + sw_off(r, u);
                ldsm_x4(&bh[g * 4], bd);
                if (TERMS == 3) ldsm_x4(&bl[g * 4], bd + 8192);
            }
#pragma unroll
            for (int mt = 0; mt < 2; mt++)
#pragma unroll
                for (int j = 0; j < 8; j++) {
                    mma_f16(acc[mt][j], ah[mt], &bh[2 * j]);
                    if (TERMS == 3) mma_f16(acc[mt][j], ah[mt], &bl[2 * j]);
                    if (TERMS >= 2) mma_f16(acc[mt][j], al[mt], &bh[2 * j]);
                }
        }
    }

    // ---- epilogue ----
    const long long cb = bz * sC;
#pragma unroll
    for (int mt = 0; mt < 2; mt++) {
        const int rb = row0 + warp_m * 32 + mt * 16 + (lane >> 2);
#pragma unroll
        for (int half = 0; half < 2; half++) {
            const long long row = rb + half * 8;
            float bm = 0.0f;
            if (BIAS_MODE == 2) bm = bias[row];
#pragma unroll
            for (int j = 0; j < 8; j++) {
                const int col = col0 + warp_n * 64 + j * 8 + (lane & 3) * 2;
                float v0 = acc[mt][j][half * 2 + 0] + bm;
                float v1 = acc[mt][j][half * 2 + 1] + bm;
                if (BIAS_MODE == 1) { v0 += bias[col]; v1 += bias[col + 1]; }
                if (OUT_MODE == 1) {
                    const __half h0 = __float2half_rn(v0);
                    const __half h1 = __float2half_rn(v1);
                    const __half l0 = __float2half_rn(v0 - __half2float(h0));
                    const __half l1 = __float2half_rn(v1 - __half2float(h1));
                    *(uint32_t*)(Ch + cb + row * (long long)N + col) = pk2h(h0, h1);
                    *(uint32_t*)(Cl + cb + row * (long long)N + col) = pk2h(l0, l1);
                } else if (OUT_MODE == 2) {
                    *(uint32_t*)(Ch + cb + row * (long long)N + col) =
                        pk2h(__float2half_rn(v0), __float2half_rn(v1));
                } else {
                    float2 vv; vv.x = v0; vv.y = v1;
                    *(float2*)(Cf + cb + row * (long long)N + col) = vv;
                }
            }
        }
    }
}

// ---------------------------------------------------------------------------
// fp32 -> fp16 hi/lo split
// ---------------------------------------------------------------------------
__global__ __launch_bounds__(256) void split2_kernel(
    const float4* __restrict__ in, uint2* __restrict__ hi, uint2* __restrict__ lo, int n4)
{
    const int i = blockIdx.x * 256 + threadIdx.x;
    if (i >= n4) return;
    const float4 v = in[i];
    const __half h0 = __float2half_rn(v.x), h1 = __float2half_rn(v.y);
    const __half h2 = __float2half_rn(v.z), h3 = __float2half_rn(v.w);
    const __half l0 = __float2half_rn(v.x - __half2float(h0));
    const __half l1 = __float2half_rn(v.y - __half2float(h1));
    const __half l2 = __float2half_rn(v.z - __half2float(h2));
    const __half l3 = __float2half_rn(v.w - __half2float(h3));
    uint2 H, L;
    H.x = pk2h(h0, h1); H.y = pk2h(h2, h3);
    L.x = pk2h(l0, l1); L.y = pk2h(l2, l3);
    hi[i] = H;  lo[i] = L;
}

// fp32 -> fp16 single
__global__ __launch_bounds__(256) void cvt1_kernel(
    const float4* __restrict__ in, uint2* __restrict__ hi, int n4)
{
    const int i = blockIdx.x * 256 + threadIdx.x;
    if (i >= n4) return;
    const float4 v = in[i];
    uint2 H;
    H.x = pk2h(__float2half_rn(v.x), __float2half_rn(v.y));
    H.y = pk2h(__float2half_rn(v.z), __float2half_rn(v.w));
    hi[i] = H;
}

// ---------------------------------------------------------------------------
// Softmax over rows of 4096 fp32 scores -> fp16 attn
// ---------------------------------------------------------------------------
__global__ __launch_bounds__(256) void softmax_kernel(
    const float* __restrict__ scores, __half* __restrict__ attn)
{
    const long long row = blockIdx.x;
    const float4* p4 = (const float4*)(scores + row * (long long)SS);
    uint2* h2 = (uint2*)(attn + row * (long long)SS);
    const int tid = threadIdx.x;
    const int lane = tid & 31;
    const int wid = tid >> 5;

    float4 r[4];
    float m = -1e30f;
#pragma unroll
    for (int i = 0; i < 4; i++) {
        r[i] = p4[tid + 256 * i];
        m = fmaxf(m, fmaxf(fmaxf(r[i].x, r[i].y), fmaxf(r[i].z, r[i].w)));
    }
#pragma unroll
    for (int o = 16; o > 0; o >>= 1) m = fmaxf(m, __shfl_xor_sync(0xffffffffu, m, o));
    __shared__ float red[8];
    if (lane == 0) red[wid] = m;
    __syncthreads();
    m = red[0];
#pragma unroll
    for (int i = 1; i < 8; i++) m = fmaxf(m, red[i]);

    float s = 0.0f;
#pragma unroll
    for (int i = 0; i < 4; i++) {
        r[i].x = __expf(r[i].x - m);  r[i].y = __expf(r[i].y - m);
        r[i].z = __expf(r[i].z - m);  r[i].w = __expf(r[i].w - m);
        s += r[i].x + r[i].y + r[i].z + r[i].w;
    }
#pragma unroll
    for (int o = 16; o > 0; o >>= 1) s += __shfl_xor_sync(0xffffffffu, s, o);
    __shared__ float red2[8];
    if (lane == 0) red2[wid] = s;
    __syncthreads();
    s = red2[0];
#pragma unroll
    for (int i = 1; i < 8; i++) s += red2[i];

    const float inv = 1.0f / s;
#pragma unroll
    for (int i = 0; i < 4; i++) {
        uint2 H;
        H.x = pk2h(__float2half_rn(r[i].x * inv), __float2half_rn(r[i].y * inv));
        H.y = pk2h(__float2half_rn(r[i].z * inv), __float2half_rn(r[i].w * inv));
        h2[tid + 256 * i] = H;
    }
}

// ---------------------------------------------------------------------------
extern "C" void kernel_launch(void* const* d_in, const int* in_sizes, int n_in,
                              void* d_out, int out_size)
{
    const float* query = (const float*)d_in[0];
    const float* key   = (const float*)d_in[1];
    const float* value = (const float*)d_in[2];
    const float* Wq    = (const float*)d_in[3];
    const float* bq    = (const float*)d_in[4];
    const float* Wk    = (const float*)d_in[5];
    const float* bk    = (const float*)d_in[6];
    const float* Wv    = (const float*)d_in[7];
    const float* bv    = (const float*)d_in[8];
    float* out = (float*)d_out;

    __half *xq_hi, *xq_lo, *xk_hi, *xk_lo, *xv_hi;
    __half *wq_hi, *wq_lo, *wk_hi, *wk_lo, *wv_hi, *wv_lo;
    __half *q_hi, *q_lo, *k_hi, *k_lo, *vt, *attn;
    float* sc;
    cudaGetSymbolAddress((void**)&xq_hi, g_xq_hi); cudaGetSymbolAddress((void**)&xq_lo, g_xq_lo);
    cudaGetSymbolAddress((void**)&xk_hi, g_xk_hi); cudaGetSymbolAddress((void**)&xk_lo, g_xk_lo);
    cudaGetSymbolAddress((void**)&xv_hi, g_xv_hi);
    cudaGetSymbolAddress((void**)&wq_hi, g_wq_hi); cudaGetSymbolAddress((void**)&wq_lo, g_wq_lo);
    cudaGetSymbolAddress((void**)&wk_hi, g_wk_hi); cudaGetSymbolAddress((void**)&wk_lo, g_wk_lo);
    cudaGetSymbolAddress((void**)&wv_hi, g_wv_hi); cudaGetSymbolAddress((void**)&wv_lo, g_wv_lo);
    cudaGetSymbolAddress((void**)&q_hi,  g_q_hi);  cudaGetSymbolAddress((void**)&q_lo,  g_q_lo);
    cudaGetSymbolAddress((void**)&k_hi,  g_k_hi);  cudaGetSymbolAddress((void**)&k_lo,  g_k_lo);
    cudaGetSymbolAddress((void**)&vt,    g_vt);
    cudaGetSymbolAddress((void**)&attn,  g_attn);
    cudaGetSymbolAddress((void**)&sc,    g_scores);

    cudaFuncSetAttribute(mma_gemm<3, 1, 1>, cudaFuncAttributeMaxDynamicSharedMemorySize, NS * StgB<3>::v);
    cudaFuncSetAttribute(mma_gemm<2, 2, 2>, cudaFuncAttributeMaxDynamicSharedMemorySize, NS * StgB<2>::v);
    cudaFuncSetAttribute(mma_gemm<3, 0, 0>, cudaFuncAttributeMaxDynamicSharedMemorySize, NS * StgB<3>::v);
    cudaFuncSetAttribute(mma_gemm<1, 0, 0>, cudaFuncAttributeMaxDynamicSharedMemorySize, NS * StgB<1>::v);

    const long long nIn = (long long)BB * SS * EE;
    const long long nW  = (long long)EE * EE;
    const long long strideQ = (long long)SS * EE;
    const long long strideS = (long long)SS * SS;
    const long long strideVT = (long long)EE * SS;

    // Launch order puts the first 3-term projection GEMM at launch index 5 so
    // the ncu capture window (-s 5 -c 1) lands on mma_gemm<3,1,1>.
    // 0-2: weight splits
    split2_kernel<<<(int)(nW / 4 / 256), 256>>>((const float4*)Wq, (uint2*)wq_hi, (uint2*)wq_lo, (int)(nW / 4));
    split2_kernel<<<(int)(nW / 4 / 256), 256>>>((const float4*)Wk, (uint2*)wk_hi, (uint2*)wk_lo, (int)(nW / 4));
    split2_kernel<<<(int)(nW / 4 / 256), 256>>>((const float4*)Wv, (uint2*)wv_hi, (uint2*)wv_lo, (int)(nW / 4));
    // 3-4: q/k input splits
    split2_kernel<<<(int)(nIn / 4 / 256), 256>>>((const float4*)query, (uint2*)xq_hi, (uint2*)xq_lo, (int)(nIn / 4));
    split2_kernel<<<(int)(nIn / 4 / 256), 256>>>((const float4*)key,   (uint2*)xk_hi, (uint2*)xk_lo, (int)(nIn / 4));

    // 5: q projection (3-term, split fp16 out, per-N bias)  <-- ncu capture slot
    {
        dim3 g(EE / 128, (BB * SS) / 128, 1);
        mma_gemm<3, 1, 1><<<g, 256, NS * StgB<3>::v>>>(xq_hi, xq_lo, wq_hi, wq_lo, bq,
                                                       nullptr, q_hi, q_lo,
                                                       BB * SS, EE, EE, 0, 0, 0);
        // 6: v input convert
        cvt1_kernel<<<(int)(nIn / 4 / 256), 256>>>((const float4*)value, (uint2*)xv_hi, (int)(nIn / 4));
        // 7: k projection
        mma_gemm<3, 1, 1><<<g, 256, NS * StgB<3>::v>>>(xk_hi, xk_lo, wk_hi, wk_lo, bk,
                                                       nullptr, k_hi, k_lo,
                                                       BB * SS, EE, EE, 0, 0, 0);
    }

    // 8: v projection, transposed (2-term; fp16 out; per-M bias)
    {
        dim3 g(SS / 128, EE / 128, BB);
        mma_gemm<2, 2, 2><<<g, 256, NS * StgB<2>::v>>>(wv_hi, wv_lo, xv_hi, nullptr, bv,
                                                       nullptr, vt, nullptr,
                                                       EE, SS, EE, 0, strideQ, strideVT);
    }

    // 9: scores = q @ k^T (3-term, fp32 out)
    {
        dim3 g(SS / 128, SS / 128, BB);
        mma_gemm<3, 0, 0><<<g, 256, NS * StgB<3>::v>>>(q_hi, q_lo, k_hi, k_lo, nullptr,
                                                       sc, nullptr, nullptr,
                                                       SS, SS, EE, strideQ, strideQ, strideS);
    }

    // 10: softmax -> fp16 attn
    softmax_kernel<<<BB * SS, 256>>>(sc, attn);

    // 11: out = attn @ vt^T (1-term, fp32 out)
    {
        dim3 g(EE / 128, SS / 128, BB);
        mma_gemm<1, 0, 0><<<g, 256, NS * StgB<1>::v>>>(attn, nullptr, vt, nullptr, nullptr,
                                                       out, nullptr, nullptr,
                                                       SS, EE, SS, strideS, strideVT, strideQ);
    }
}